// round 14
// baseline (speedup 1.0000x reference)
#include <cuda_runtime.h>
#include <math.h>
#include <stdint.h>

#define Dm 2048
#define MT 128
#define KC 32
#define NCH 64

// float-index smem offsets
#define XS0 0          // 32 x 132
#define XS1 4224       // GEMM x region ends 8448
#define EMBF 0         // 128x132, aliases x bufs post-GEMM
#define ESTR 132
#define WDTF 16896     // 128x128
#define GTF  33280     // 128x132
#define ABFI 50176     // 8 warps x 128
#define RNNF 51200
#define GAMF 51328
#define BETF 51456
#define SMEM_SZ (51584 * 4)

__device__ float g_WrT[Dm * 128];   // [k][e] plain
__device__ float g_WdT[128 * 128];  // [e][swizzled h-blocks]

typedef unsigned long long ull;

__device__ __forceinline__ void fma2(ull& d, ull a, ull b) {
    asm("fma.rn.f32x2 %0, %1, %2, %0;" : "+l"(d) : "l"(a), "l"(b));
}
__device__ __forceinline__ float2 up2(ull v) {
    float2 r; asm("mov.b64 {%0, %1}, %2;" : "=f"(r.x), "=f"(r.y) : "l"(v)); return r;
}
__device__ __forceinline__ ull pk2(float x, float y) {
    ull r; asm("mov.b64 %0, {%1, %2};" : "=l"(r) : "f"(x), "f"(y)); return r;
}
__device__ __forceinline__ ull swp(ull v) { float2 f = up2(v); return pk2(f.y, f.x); }

__global__ void prep_kernel(const float* __restrict__ Wr, const float* __restrict__ Wd) {
    int i = blockIdx.x * 256 + threadIdx.x;   // over E*Dm, k fastest
    int e = i >> 11, k = i & 2047;
    g_WrT[k * 128 + e] = Wr[i];
    if (i < 128 * 128) {
        int h = i >> 7, ee = i & 127;
        int bb = h >> 2, sbb = bb ^ (bb >> 3);
        g_WdT[ee * 128 + sbb * 4 + (h & 3)] = Wd[i];
    }
}

__global__ __launch_bounds__(256, 1) void fused_kernel(
    const float* __restrict__ x, const float* __restrict__ gumbel,
    const float* __restrict__ rnn_g, const float* __restrict__ gamma_g,
    const float* __restrict__ beta_g, const int* __restrict__ topk_p,
    float* __restrict__ out_bin, float* __restrict__ out_ap)
{
    extern __shared__ float fs[];
    const int tid = threadIdx.x;
    const int wid = tid >> 5;
    const int lane = tid & 31;
    const int t0 = blockIdx.x * MT;
    const float* xg = x + (size_t)t0 * Dm;

    // ---- stage decoder weights + LN params (disjoint from GEMM x buffers) ----
#pragma unroll
    for (int p = 0; p < 16; p++) {
        int n = tid + 256 * p;
        *(float4*)&fs[WDTF + n * 4] = *(const float4*)&g_WdT[n * 4];
    }
    if (tid < 128) {
        fs[RNNF + tid] = rnn_g[tid];
        fs[GAMF + tid] = gamma_g[tid];
        fs[BETF + tid] = beta_g[tid];
    }

    // ---- GEMM1: 8x8 tiles; A from smem (broadcast), B via __ldg (L1-resident) ----
    const int tm = tid >> 4;
    const int te = tid & 15;
    // u2 units: row k of g_WrT = 32 u2; this thread's 8 floats start at u2 (k*32)
    const ulonglong2* wr = (const ulonglong2*)(g_WrT + 8 * te);

    ull P[4][4], Q[4][4];
#pragma unroll
    for (int i = 0; i < 4; i++)
#pragma unroll
        for (int j = 0; j < 4; j++) { P[i][j] = 0ull; Q[i][j] = 0ull; }

    float4 xf[4];

#define LOAD_CHUNK(k0)                                                              \
    {                                                                               \
        _Pragma("unroll")                                                           \
        for (int p = 0; p < 4; p++) {                                               \
            int idx = tid + 256 * p;                                                \
            xf[p] = *(const float4*)&xg[(size_t)(idx >> 3) * Dm + (k0) + (idx & 7) * 4]; \
        }                                                                           \
    }
#define STORE_CHUNK(xdst)                                                           \
    {                                                                               \
        _Pragma("unroll")                                                           \
        for (int p = 0; p < 4; p++) {                                               \
            int idx = tid + 256 * p, m = idx >> 3, kq = (idx & 7) * 4;              \
            fs[(xdst) + (kq + 0) * 132 + m] = xf[p].x;                              \
            fs[(xdst) + (kq + 1) * 132 + m] = xf[p].y;                              \
            fs[(xdst) + (kq + 2) * 132 + m] = xf[p].z;                              \
            fs[(xdst) + (kq + 3) * 132 + m] = xf[p].w;                              \
        }                                                                           \
    }

    LOAD_CHUNK(0);
    STORE_CHUNK(XS0);
    LOAD_CHUNK(KC);
    __syncthreads();

    for (int ch = 0; ch < NCH; ++ch) {
        const int cur = ch & 1;
        if (ch + 1 < NCH) {
            if (cur) STORE_CHUNK(XS0) else STORE_CHUNK(XS1);
        }
        if (ch + 2 < NCH) LOAD_CHUNK((ch + 2) * KC);

        const int xb = (cur ? XS1 : XS0) + 8 * tm;
        const int kg0 = ch * KC;

        // register double-buffer over k
        ulonglong2 cA0 = *(const ulonglong2*)&fs[xb];
        ulonglong2 cA1 = *(const ulonglong2*)&fs[xb + 4];
        ulonglong2 cB0 = __ldg(wr + (size_t)kg0 * 32);
        ulonglong2 cB1 = __ldg(wr + (size_t)kg0 * 32 + 1);
#pragma unroll
        for (int k = 0; k < KC; ++k) {
            ulonglong2 nA0, nA1, nB0, nB1;
            if (k + 1 < KC) {
                nA0 = *(const ulonglong2*)&fs[xb + (k + 1) * 132];
                nA1 = *(const ulonglong2*)&fs[xb + (k + 1) * 132 + 4];
                nB0 = __ldg(wr + (size_t)(kg0 + k + 1) * 32);
                nB1 = __ldg(wr + (size_t)(kg0 + k + 1) * 32 + 1);
            }
            ull ap[4] = {cA0.x, cA0.y, cA1.x, cA1.y};
            ull bp[4] = {cB0.x, cB0.y, cB1.x, cB1.y};
            ull sp[4] = {swp(cB0.x), swp(cB0.y), swp(cB1.x), swp(cB1.y)};
#pragma unroll
            for (int i = 0; i < 4; i++)
#pragma unroll
                for (int j = 0; j < 4; j++) {
                    fma2(P[i][j], ap[i], bp[j]);
                    fma2(Q[i][j], ap[i], sp[j]);
                }
            cA0 = nA0; cA1 = nA1; cB0 = nB0; cB1 = nB1;
        }
        __syncthreads();
    }

    // unpack emb (aliases x buffers): P=(a0b0,a1b1), Q=(a0b1,a1b0)
#pragma unroll
    for (int i = 0; i < 4; i++)
#pragma unroll
        for (int j = 0; j < 4; j++) {
            float2 p = up2(P[i][j]), q = up2(Q[i][j]);
            int m0 = 8 * tm + 2 * i, e0 = 8 * te + 2 * j;
            *(float2*)&fs[EMBF + m0 * ESTR + e0]       = make_float2(p.x, q.x);
            *(float2*)&fs[EMBF + (m0 + 1) * ESTR + e0] = make_float2(q.y, p.y);
        }
    __syncthreads();

    // ---- LN + GELU -> gT[e][tok] ----
    for (int tt = 0; tt < 16; ++tt) {
        const int t = wid * 16 + tt;
        float v[4];
#pragma unroll
        for (int j = 0; j < 4; j++) {
            int e = lane + 32 * j;
            v[j] = fs[EMBF + t * ESTR + e] + fs[RNNF + e];
        }
        float s = v[0] + v[1] + v[2] + v[3];
#pragma unroll
        for (int o = 16; o > 0; o >>= 1) s += __shfl_xor_sync(0xffffffffu, s, o);
        const float mu = s * (1.0f / 128.0f);
        float q = 0.f;
#pragma unroll
        for (int j = 0; j < 4; j++) { float d = v[j] - mu; q += d * d; }
#pragma unroll
        for (int o = 16; o > 0; o >>= 1) q += __shfl_xor_sync(0xffffffffu, q, o);
        const float inv = rsqrtf(q * (1.0f / 128.0f) + 1e-5f);
#pragma unroll
        for (int j = 0; j < 4; j++) {
            int e = lane + 32 * j;
            float h = (v[j] - mu) * inv * fs[GAMF + e] + fs[BETF + e];
            fs[GTF + e * 132 + t] = 0.5f * h * (1.0f + erff(h * 0.70710678118654752f));
        }
    }
    __syncthreads();

    // ---- GEMM2 (tiled scalar FFMA2): logits = g @ WdT ----
    {
        const int b0 = 2 * te, b1 = 2 * te + 1;
        const int s0 = b0 ^ (b0 >> 3), s1 = b1 ^ (b1 >> 3);
        ull P2[4][4], Q2[4][4];
#pragma unroll
        for (int i = 0; i < 4; i++)
#pragma unroll
            for (int j = 0; j < 4; j++) { P2[i][j] = 0ull; Q2[i][j] = 0ull; }

#pragma unroll 4
        for (int e = 0; e < 128; ++e) {
            ulonglong2 aA = *(const ulonglong2*)&fs[GTF + e * 132 + 8 * tm];
            ulonglong2 aB = *(const ulonglong2*)&fs[GTF + e * 132 + 8 * tm + 4];
            ull av[4] = {aA.x, aA.y, aB.x, aB.y};
            ull sv[4] = {swp(aA.x), swp(aA.y), swp(aB.x), swp(aB.y)};
            ulonglong2 Bx = *(const ulonglong2*)&fs[WDTF + e * 128 + 4 * s0];
            ulonglong2 By = *(const ulonglong2*)&fs[WDTF + e * 128 + 4 * s1];
            ull bv[4] = {Bx.x, Bx.y, By.x, By.y};
#pragma unroll
            for (int i = 0; i < 4; i++)
#pragma unroll
                for (int j = 0; j < 4; j++) {
                    fma2(P2[i][j], av[i], bv[j]);
                    fma2(Q2[i][j], sv[i], bv[j]);
                }
        }
        __syncthreads();
#pragma unroll
        for (int i = 0; i < 4; i++)
#pragma unroll
            for (int j = 0; j < 4; j++) {
                float2 p = up2(P2[i][j]), q = up2(Q2[i][j]);
                int r0 = 8 * tm + 2 * i, c0 = 8 * te + 2 * j;
                *(float2*)&fs[EMBF + r0 * ESTR + c0]       = make_float2(p.x, q.y);
                *(float2*)&fs[EMBF + (r0 + 1) * ESTR + c0] = make_float2(q.x, p.y);
            }
    }
    __syncthreads();

    // ---- gumbel-sigmoid + round + top-k mask ----
    const int K = *topk_p;
    const float Kf = (float)K;

    for (int tt = 0; tt < 16; ++tt) {
        const int t = wid * 16 + tt;
        const int gt = t0 + t;

        float4 lgv = *(const float4*)&fs[EMBF + t * ESTR + lane * 4];
        float lg[4] = {lgv.x, lgv.y, lgv.z, lgv.w};
        float4 gu = *(const float4*)&gumbel[(size_t)gt * 128 + lane * 4];
        float gua[4] = {gu.x, gu.y, gu.z, gu.w};

        float ap[4], bn[4];
        float csum = 0.f;
#pragma unroll
        for (int jj = 0; jj < 4; jj++) {
            float z = (lg[jj] + gua[jj] + 3.0f) * 2.5f;
            ap[jj] = 1.0f / (1.0f + expf(-z));
            bn[jj] = rintf(ap[jj]);
            csum += bn[jj];
        }
#pragma unroll
        for (int o = 16; o > 0; o >>= 1) csum += __shfl_xor_sync(0xffffffffu, csum, o);

        float ob[4];
        if (csum > Kf || csum == 0.0f) {
            const int kneed = (csum > Kf) ? K : 1;
#pragma unroll
            for (int jj = 0; jj < 4; jj++) fs[ABFI + wid * 128 + lane * 4 + jj] = ap[jj];
            __syncwarp();
            int r[4] = {0, 0, 0, 0};
            for (int j4 = 0; j4 < 128; j4 += 4) {
                float4 av = *(const float4*)&fs[ABFI + wid * 128 + j4];
                float aj[4] = {av.x, av.y, av.z, av.w};
#pragma unroll
                for (int u = 0; u < 4; u++) {
                    int j = j4 + u;
#pragma unroll
                    for (int jj = 0; jj < 4; jj++) {
                        int idx = lane * 4 + jj;
                        r[jj] += (aj[u] > ap[jj]) || (aj[u] == ap[jj] && j < idx);
                    }
                }
            }
#pragma unroll
            for (int jj = 0; jj < 4; jj++) ob[jj] = (r[jj] < kneed) ? 1.0f : 0.0f;
            __syncwarp();
        } else {
#pragma unroll
            for (int jj = 0; jj < 4; jj++) ob[jj] = bn[jj];
        }

        *(float4*)&out_bin[(size_t)gt * 128 + lane * 4] = make_float4(ob[0], ob[1], ob[2], ob[3]);
        if (out_ap)
            *(float4*)&out_ap[(size_t)gt * 128 + lane * 4] = make_float4(ap[0], ap[1], ap[2], ap[3]);
    }
}

extern "C" void kernel_launch(void* const* d_in, const int* in_sizes, int n_in,
                              void* d_out, int out_size) {
    const float* x        = (const float*)d_in[0];
    const float* W_router = (const float*)d_in[1];
    const float* W_dec    = (const float*)d_in[2];
    const float* ln_gamma = (const float*)d_in[3];
    const float* ln_beta  = (const float*)d_in[4];
    const float* rnn      = (const float*)d_in[5];
    const float* gumbel   = (const float*)d_in[6];
    const int*   topk     = (const int*)d_in[7];

    float* out_bin = (float*)d_out;
    const size_t N = (size_t)16384 * 128;
    float* out_ap = ((size_t)out_size >= 2 * N) ? out_bin + N : nullptr;

    prep_kernel<<<(128 * Dm) / 256, 256>>>(W_router, W_dec);

    cudaFuncSetAttribute(fused_kernel, cudaFuncAttributeMaxDynamicSharedMemorySize, SMEM_SZ);
    fused_kernel<<<16384 / MT, 256, SMEM_SZ>>>(
        x, gumbel, rnn, ln_gamma, ln_beta, topk, out_bin, out_ap);
}

// round 15
// speedup vs baseline: 1.3887x; 1.3887x over previous
#include <cuda_runtime.h>
#include <math.h>
#include <stdint.h>

#define Dm 2048
#define MT 128
#define KC 32
#define NCH 64

// float-index smem offsets
#define XS0 0
#define WS0 4224
#define XS1 8448
#define WS1 12672
#define EMBF 0         // 128x132, aliases GEMM bufs post-GEMM
#define ESTR 132
#define WDTF 16896     // 128x128
#define GTF  33280     // 128x132
#define RNNF 50176
#define GAMF 50304
#define BETF 50432
#define SMEM_SZ (50560 * 4)

__device__ float g_WrT[Dm * 128];   // [k][swizzled e-blocks]
__device__ float g_WdT[128 * 128];  // [e][swizzled h-blocks]

typedef unsigned long long ull;

__device__ __forceinline__ void fma2(ull& d, ull a, ull b) {
    asm("fma.rn.f32x2 %0, %1, %2, %0;" : "+l"(d) : "l"(a), "l"(b));
}
__device__ __forceinline__ float2 up2(ull v) {
    float2 r; asm("mov.b64 {%0, %1}, %2;" : "=f"(r.x), "=f"(r.y) : "l"(v)); return r;
}
__device__ __forceinline__ ull pk2(float x, float y) {
    ull r; asm("mov.b64 %0, {%1, %2};" : "=l"(r) : "f"(x), "f"(y)); return r;
}
__device__ __forceinline__ ull swp(ull v) { float2 f = up2(v); return pk2(f.y, f.x); }

__global__ void prep_kernel(const float* __restrict__ Wr, const float* __restrict__ Wd) {
    int i = blockIdx.x * 256 + threadIdx.x;   // over E*Dm, k fastest
    int e = i >> 11, k = i & 2047;
    int b = e >> 2, sb = b ^ (b >> 3);
    g_WrT[k * 128 + sb * 4 + (e & 3)] = Wr[i];
    if (i < 128 * 128) {
        int h = i >> 7, ee = i & 127;
        int bb = h >> 2, sbb = bb ^ (bb >> 3);
        g_WdT[ee * 128 + sbb * 4 + (h & 3)] = Wd[i];
    }
}

__global__ __launch_bounds__(256, 1) void fused_kernel(
    const float* __restrict__ x, const float* __restrict__ gumbel,
    const float* __restrict__ rnn_g, const float* __restrict__ gamma_g,
    const float* __restrict__ beta_g, const int* __restrict__ topk_p,
    float* __restrict__ out_bin, float* __restrict__ out_ap)
{
    extern __shared__ float fs[];
    const int tid = threadIdx.x;
    const int wid = tid >> 5;
    const int lane = tid & 31;
    const int t0 = blockIdx.x * MT;
    const float* xg = x + (size_t)t0 * Dm;

    // ---- stage decoder weights + LN params (disjoint from GEMM buffers) ----
#pragma unroll
    for (int p = 0; p < 16; p++) {
        int n = tid + 256 * p;
        *(float4*)&fs[WDTF + n * 4] = *(const float4*)&g_WdT[n * 4];
    }
    if (tid < 128) {
        fs[RNNF + tid] = rnn_g[tid];
        fs[GAMF + tid] = gamma_g[tid];
        fs[BETF + tid] = beta_g[tid];
    }

    // ---- GEMM1: 8x8 thread tiles, diagonal FFMA2, double-buffered 1-sync ----
    const int tm = tid >> 4;
    const int te = tid & 15;
    const int b0 = 2 * te, b1 = 2 * te + 1;
    const int s0 = b0 ^ (b0 >> 3), s1 = b1 ^ (b1 >> 3);

    ull P[4][4], Q[4][4];
#pragma unroll
    for (int i = 0; i < 4; i++)
#pragma unroll
        for (int j = 0; j < 4; j++) { P[i][j] = 0ull; Q[i][j] = 0ull; }

    float4 xf[4], wf[4];

#define LOAD_CHUNK(k0)                                                              \
    {                                                                               \
        _Pragma("unroll")                                                           \
        for (int p = 0; p < 4; p++) {                                               \
            int idx = tid + 256 * p;                                                \
            xf[p] = *(const float4*)&xg[(size_t)(idx >> 3) * Dm + (k0) + (idx & 7) * 4]; \
            wf[p] = *(const float4*)&g_WrT[((k0) + (idx >> 5)) * 128 + (idx & 31) * 4];  \
        }                                                                           \
    }
#define STORE_CHUNK(xdst, wdst)                                                     \
    {                                                                               \
        _Pragma("unroll")                                                           \
        for (int p = 0; p < 4; p++) {                                               \
            int idx = tid + 256 * p, m = idx >> 3, kq = (idx & 7) * 4;              \
            fs[(xdst) + (kq + 0) * 132 + m] = xf[p].x;                              \
            fs[(xdst) + (kq + 1) * 132 + m] = xf[p].y;                              \
            fs[(xdst) + (kq + 2) * 132 + m] = xf[p].z;                              \
            fs[(xdst) + (kq + 3) * 132 + m] = xf[p].w;                              \
            *(float4*)&fs[(wdst) + (idx >> 5) * 132 + (idx & 31) * 4] = wf[p];      \
        }                                                                           \
    }

    LOAD_CHUNK(0);
    STORE_CHUNK(XS0, WS0);
    LOAD_CHUNK(KC);
    __syncthreads();

    for (int ch = 0; ch < NCH; ++ch) {
        const int cur = ch & 1;
        if (ch + 1 < NCH) {
            if (cur) STORE_CHUNK(XS0, WS0) else STORE_CHUNK(XS1, WS1);
        }
        if (ch + 2 < NCH) LOAD_CHUNK((ch + 2) * KC);

        const int xb = (cur ? XS1 : XS0) + 8 * tm;
        const int w0 = (cur ? WS1 : WS0) + 4 * s0;
        const int w1 = (cur ? WS1 : WS0) + 4 * s1;

        ulonglong2 cA0 = *(const ulonglong2*)&fs[xb];
        ulonglong2 cA1 = *(const ulonglong2*)&fs[xb + 4];
        ulonglong2 cB0 = *(const ulonglong2*)&fs[w0];
        ulonglong2 cB1 = *(const ulonglong2*)&fs[w1];
#pragma unroll
        for (int k = 0; k < KC; ++k) {
            ulonglong2 nA0, nA1, nB0, nB1;
            if (k + 1 < KC) {
                nA0 = *(const ulonglong2*)&fs[xb + (k + 1) * 132];
                nA1 = *(const ulonglong2*)&fs[xb + (k + 1) * 132 + 4];
                nB0 = *(const ulonglong2*)&fs[w0 + (k + 1) * 132];
                nB1 = *(const ulonglong2*)&fs[w1 + (k + 1) * 132];
            }
            ull ap[4] = {cA0.x, cA0.y, cA1.x, cA1.y};
            ull bp[4] = {cB0.x, cB0.y, cB1.x, cB1.y};
            ull sp[4] = {swp(cB0.x), swp(cB0.y), swp(cB1.x), swp(cB1.y)};
#pragma unroll
            for (int i = 0; i < 4; i++)
#pragma unroll
                for (int j = 0; j < 4; j++) {
                    fma2(P[i][j], ap[i], bp[j]);
                    fma2(Q[i][j], ap[i], sp[j]);
                }
            cA0 = nA0; cA1 = nA1; cB0 = nB0; cB1 = nB1;
        }
        __syncthreads();
    }

    // unpack emb (aliases GEMM buffers): P=(a0b0,a1b1), Q=(a0b1,a1b0)
#pragma unroll
    for (int i = 0; i < 4; i++)
#pragma unroll
        for (int j = 0; j < 4; j++) {
            float2 p = up2(P[i][j]), q = up2(Q[i][j]);
            int m0 = 8 * tm + 2 * i, e0 = 8 * te + 2 * j;
            *(float2*)&fs[EMBF + m0 * ESTR + e0]       = make_float2(p.x, q.x);
            *(float2*)&fs[EMBF + (m0 + 1) * ESTR + e0] = make_float2(q.y, p.y);
        }
    __syncthreads();

    // ---- LN + GELU -> gT[e][tok] ----
    for (int tt = 0; tt < 16; ++tt) {
        const int t = wid * 16 + tt;
        float v[4];
#pragma unroll
        for (int j = 0; j < 4; j++) {
            int e = lane + 32 * j;
            v[j] = fs[EMBF + t * ESTR + e] + fs[RNNF + e];
        }
        float s = v[0] + v[1] + v[2] + v[3];
#pragma unroll
        for (int o = 16; o > 0; o >>= 1) s += __shfl_xor_sync(0xffffffffu, s, o);
        const float mu = s * (1.0f / 128.0f);
        float q = 0.f;
#pragma unroll
        for (int j = 0; j < 4; j++) { float d = v[j] - mu; q += d * d; }
#pragma unroll
        for (int o = 16; o > 0; o >>= 1) q += __shfl_xor_sync(0xffffffffu, q, o);
        const float inv = rsqrtf(q * (1.0f / 128.0f) + 1e-5f);
#pragma unroll
        for (int j = 0; j < 4; j++) {
            int e = lane + 32 * j;
            float h = (v[j] - mu) * inv * fs[GAMF + e] + fs[BETF + e];
            fs[GTF + e * 132 + t] = 0.5f * h * (1.0f + erff(h * 0.70710678118654752f));
        }
    }
    __syncthreads();

    // ---- GEMM2 (tiled scalar FFMA2): logits = g @ WdT ----
    {
        ull P2[4][4], Q2[4][4];
#pragma unroll
        for (int i = 0; i < 4; i++)
#pragma unroll
            for (int j = 0; j < 4; j++) { P2[i][j] = 0ull; Q2[i][j] = 0ull; }

#pragma unroll 4
        for (int e = 0; e < 128; ++e) {
            ulonglong2 aA = *(const ulonglong2*)&fs[GTF + e * 132 + 8 * tm];
            ulonglong2 aB = *(const ulonglong2*)&fs[GTF + e * 132 + 8 * tm + 4];
            ull av[4] = {aA.x, aA.y, aB.x, aB.y};
            ull sv[4] = {swp(aA.x), swp(aA.y), swp(aB.x), swp(aB.y)};
            ulonglong2 Bx = *(const ulonglong2*)&fs[WDTF + e * 128 + 4 * s0];
            ulonglong2 By = *(const ulonglong2*)&fs[WDTF + e * 128 + 4 * s1];
            ull bv[4] = {Bx.x, Bx.y, By.x, By.y};
#pragma unroll
            for (int i = 0; i < 4; i++)
#pragma unroll
                for (int j = 0; j < 4; j++) {
                    fma2(P2[i][j], av[i], bv[j]);
                    fma2(Q2[i][j], sv[i], bv[j]);
                }
        }
        __syncthreads();
#pragma unroll
        for (int i = 0; i < 4; i++)
#pragma unroll
            for (int j = 0; j < 4; j++) {
                float2 p = up2(P2[i][j]), q = up2(Q2[i][j]);
                int r0 = 8 * tm + 2 * i, c0 = 8 * te + 2 * j;
                *(float2*)&fs[EMBF + r0 * ESTR + c0]       = make_float2(p.x, q.y);
                *(float2*)&fs[EMBF + (r0 + 1) * ESTR + c0] = make_float2(q.x, p.y);
            }
    }
    __syncthreads();

    // ---- gumbel-sigmoid + round + exact top-k via bitwise binary search ----
    const int K = *topk_p;
    const float Kf = (float)K;
    const uint32_t ltm = (1u << lane) - 1u;

    for (int tt = 0; tt < 16; ++tt) {
        const int t = wid * 16 + tt;
        const int gt = t0 + t;

        float4 lgv = *(const float4*)&fs[EMBF + t * ESTR + lane * 4];
        float lg[4] = {lgv.x, lgv.y, lgv.z, lgv.w};
        float4 gu = *(const float4*)&gumbel[(size_t)gt * 128 + lane * 4];
        float gua[4] = {gu.x, gu.y, gu.z, gu.w};

        float ap[4], bn[4];
        float csum = 0.f;
#pragma unroll
        for (int jj = 0; jj < 4; jj++) {
            float z = (lg[jj] + gua[jj] + 3.0f) * 2.5f;
            ap[jj] = 1.0f / (1.0f + expf(-z));
            bn[jj] = rintf(ap[jj]);
            csum += bn[jj];
        }
#pragma unroll
        for (int o = 16; o > 0; o >>= 1) csum += __shfl_xor_sync(0xffffffffu, csum, o);

        float ob[4];
        if (csum > Kf || csum == 0.0f) {   // warp-uniform
            const int kneed = (csum > Kf) ? K : 1;
            uint32_t ub[4];
#pragma unroll
            for (int jj = 0; jj < 4; jj++) ub[jj] = __float_as_uint(ap[jj]);

            // T = kneed-th largest value (exact): ap in (0,1] -> bits <= 0x3F800000 (bit 29 max)
            uint32_t T = 0;
#pragma unroll
            for (int b = 29; b >= 0; --b) {
                uint32_t cand = T | (1u << b);
                int c = (ub[0] >= cand) + (ub[1] >= cand) + (ub[2] >= cand) + (ub[3] >= cand);
                if (__reduce_add_sync(0xffffffffu, c) >= kneed) T = cand;
            }
            int cg = (ub[0] > T) + (ub[1] > T) + (ub[2] > T) + (ub[3] > T);
            const int need = kneed - __reduce_add_sync(0xffffffffu, cg);

            // ties at T broken by ascending index (idx = lane*4 + jj)
            uint32_t bm[4];
#pragma unroll
            for (int jj = 0; jj < 4; jj++) bm[jj] = __ballot_sync(0xffffffffu, ub[jj] == T);
            int base = __popc(bm[0] & ltm) + __popc(bm[1] & ltm) +
                       __popc(bm[2] & ltm) + __popc(bm[3] & ltm);
            int pre = 0;
#pragma unroll
            for (int jj = 0; jj < 4; jj++) {
                int tr = base + pre;
                ob[jj] = (ub[jj] > T || (ub[jj] == T && tr < need)) ? 1.0f : 0.0f;
                pre += (bm[jj] >> lane) & 1u;
            }
        } else {
#pragma unroll
            for (int jj = 0; jj < 4; jj++) ob[jj] = bn[jj];
        }

        *(float4*)&out_bin[(size_t)gt * 128 + lane * 4] = make_float4(ob[0], ob[1], ob[2], ob[3]);
        if (out_ap)
            *(float4*)&out_ap[(size_t)gt * 128 + lane * 4] = make_float4(ap[0], ap[1], ap[2], ap[3]);
    }
}

extern "C" void kernel_launch(void* const* d_in, const int* in_sizes, int n_in,
                              void* d_out, int out_size) {
    const float* x        = (const float*)d_in[0];
    const float* W_router = (const float*)d_in[1];
    const float* W_dec    = (const float*)d_in[2];
    const float* ln_gamma = (const float*)d_in[3];
    const float* ln_beta  = (const float*)d_in[4];
    const float* rnn      = (const float*)d_in[5];
    const float* gumbel   = (const float*)d_in[6];
    const int*   topk     = (const int*)d_in[7];

    float* out_bin = (float*)d_out;
    const size_t N = (size_t)16384 * 128;
    float* out_ap = ((size_t)out_size >= 2 * N) ? out_bin + N : nullptr;

    prep_kernel<<<(128 * Dm) / 256, 256>>>(W_router, W_dec);

    cudaFuncSetAttribute(fused_kernel, cudaFuncAttributeMaxDynamicSharedMemorySize, SMEM_SZ);
    fused_kernel<<<16384 / MT, 256, SMEM_SZ>>>(
        x, gumbel, rnn, ln_gamma, ln_beta, topk, out_bin, out_ap);
}

// round 17
// speedup vs baseline: 1.4105x; 1.0157x over previous
#include <cuda_runtime.h>
#include <math.h>
#include <stdint.h>

#define Dm 2048
#define MT 128
#define KC 32
#define NCH 64

// float-index smem offsets
#define XS0 0
#define WS0 4224
#define XS1 8448
#define WS1 12672
#define EMBF 0         // 128x132, aliases GEMM bufs post-GEMM
#define ESTR 132
#define WDTF 16896     // 128x128
#define GTF  33280     // 128x132 (16B-aligned stride)
#define GTS  132
#define RNNF 50176
#define GAMF 50304
#define BETF 50432
#define SMEM_SZ (50560 * 4)

__device__ float g_WrT[Dm * 128];   // [k][swizzled e-blocks]
__device__ float g_WdT[128 * 128];  // [e][swizzled h-blocks]

typedef unsigned long long ull;

__device__ __forceinline__ void fma2(ull& d, ull a, ull b) {
    asm("fma.rn.f32x2 %0, %1, %2, %0;" : "+l"(d) : "l"(a), "l"(b));
}
__device__ __forceinline__ float2 up2(ull v) {
    float2 r; asm("mov.b64 {%0, %1}, %2;" : "=f"(r.x), "=f"(r.y) : "l"(v)); return r;
}
__device__ __forceinline__ ull pk2(float x, float y) {
    ull r; asm("mov.b64 %0, {%1, %2};" : "=l"(r) : "f"(x), "f"(y)); return r;
}
__device__ __forceinline__ ull swp(ull v) { float2 f = up2(v); return pk2(f.y, f.x); }

__global__ void prep_kernel(const float* __restrict__ Wr, const float* __restrict__ Wd) {
    int i = blockIdx.x * 256 + threadIdx.x;   // over E*Dm, k fastest
    int e = i >> 11, k = i & 2047;
    int b = e >> 2, sb = b ^ (b >> 3);
    g_WrT[k * 128 + sb * 4 + (e & 3)] = Wr[i];
    if (i < 128 * 128) {
        int h = i >> 7, ee = i & 127;
        int bb = h >> 2, sbb = bb ^ (bb >> 3);
        g_WdT[ee * 128 + sbb * 4 + (h & 3)] = Wd[i];
    }
}

__global__ __launch_bounds__(256, 1) void fused_kernel(
    const float* __restrict__ x, const float* __restrict__ gumbel,
    const float* __restrict__ rnn_g, const float* __restrict__ gamma_g,
    const float* __restrict__ beta_g, const int* __restrict__ topk_p,
    float* __restrict__ out_bin, float* __restrict__ out_ap)
{
    extern __shared__ float fs[];
    const int tid = threadIdx.x;
    const int wid = tid >> 5;
    const int lane = tid & 31;
    const int t0 = blockIdx.x * MT;
    const float* xg = x + (size_t)t0 * Dm;

    // ---- stage decoder weights + LN params (disjoint from GEMM buffers) ----
#pragma unroll
    for (int p = 0; p < 16; p++) {
        int n = tid + 256 * p;
        *(float4*)&fs[WDTF + n * 4] = *(const float4*)&g_WdT[n * 4];
    }
    if (tid < 128) {
        fs[RNNF + tid] = rnn_g[tid];
        fs[GAMF + tid] = gamma_g[tid];
        fs[BETF + tid] = beta_g[tid];
    }

    // ---- GEMM1: 8x8 thread tiles, diagonal FFMA2, double-buffered 1-sync ----
    const int tm = tid >> 4;
    const int te = tid & 15;
    const int b0 = 2 * te, b1 = 2 * te + 1;
    const int s0 = b0 ^ (b0 >> 3), s1 = b1 ^ (b1 >> 3);

    ull P[4][4], Q[4][4];
#pragma unroll
    for (int i = 0; i < 4; i++)
#pragma unroll
        for (int j = 0; j < 4; j++) { P[i][j] = 0ull; Q[i][j] = 0ull; }

    float4 xf[4], wf[4];

#define LOAD_CHUNK(k0)                                                              \
    {                                                                               \
        _Pragma("unroll")                                                           \
        for (int p = 0; p < 4; p++) {                                               \
            int idx = tid + 256 * p;                                                \
            xf[p] = *(const float4*)&xg[(size_t)(idx >> 3) * Dm + (k0) + (idx & 7) * 4]; \
            wf[p] = *(const float4*)&g_WrT[((k0) + (idx >> 5)) * 128 + (idx & 31) * 4];  \
        }                                                                           \
    }
#define STORE_CHUNK(xdst, wdst)                                                     \
    {                                                                               \
        _Pragma("unroll")                                                           \
        for (int p = 0; p < 4; p++) {                                               \
            int idx = tid + 256 * p, m = idx >> 3, kq = (idx & 7) * 4;              \
            fs[(xdst) + (kq + 0) * 132 + m] = xf[p].x;                              \
            fs[(xdst) + (kq + 1) * 132 + m] = xf[p].y;                              \
            fs[(xdst) + (kq + 2) * 132 + m] = xf[p].z;                              \
            fs[(xdst) + (kq + 3) * 132 + m] = xf[p].w;                              \
            *(float4*)&fs[(wdst) + (idx >> 5) * 132 + (idx & 31) * 4] = wf[p];      \
        }                                                                           \
    }

    LOAD_CHUNK(0);
    STORE_CHUNK(XS0, WS0);
    LOAD_CHUNK(KC);
    __syncthreads();

    for (int ch = 0; ch < NCH; ++ch) {
        const int cur = ch & 1;
        if (ch + 1 < NCH) {
            if (cur) STORE_CHUNK(XS0, WS0) else STORE_CHUNK(XS1, WS1);
        }
        if (ch + 2 < NCH) LOAD_CHUNK((ch + 2) * KC);

        const int xb = (cur ? XS1 : XS0) + 8 * tm;
        const int w0 = (cur ? WS1 : WS0) + 4 * s0;
        const int w1 = (cur ? WS1 : WS0) + 4 * s1;

        ulonglong2 cA0 = *(const ulonglong2*)&fs[xb];
        ulonglong2 cA1 = *(const ulonglong2*)&fs[xb + 4];
        ulonglong2 cB0 = *(const ulonglong2*)&fs[w0];
        ulonglong2 cB1 = *(const ulonglong2*)&fs[w1];
#pragma unroll
        for (int k = 0; k < KC; ++k) {
            ulonglong2 nA0, nA1, nB0, nB1;
            if (k + 1 < KC) {
                nA0 = *(const ulonglong2*)&fs[xb + (k + 1) * 132];
                nA1 = *(const ulonglong2*)&fs[xb + (k + 1) * 132 + 4];
                nB0 = *(const ulonglong2*)&fs[w0 + (k + 1) * 132];
                nB1 = *(const ulonglong2*)&fs[w1 + (k + 1) * 132];
            }
            ull ap[4] = {cA0.x, cA0.y, cA1.x, cA1.y};
            ull bp[4] = {cB0.x, cB0.y, cB1.x, cB1.y};
            ull sp[4] = {swp(cB0.x), swp(cB0.y), swp(cB1.x), swp(cB1.y)};
#pragma unroll
            for (int i = 0; i < 4; i++)
#pragma unroll
                for (int j = 0; j < 4; j++) {
                    fma2(P[i][j], ap[i], bp[j]);
                    fma2(Q[i][j], ap[i], sp[j]);
                }
            cA0 = nA0; cA1 = nA1; cB0 = nB0; cB1 = nB1;
        }
        __syncthreads();
    }

    // unpack emb (aliases GEMM buffers): P=(a0b0,a1b1), Q=(a0b1,a1b0)
#pragma unroll
    for (int i = 0; i < 4; i++)
#pragma unroll
        for (int j = 0; j < 4; j++) {
            float2 p = up2(P[i][j]), q = up2(Q[i][j]);
            int m0 = 8 * tm + 2 * i, e0 = 8 * te + 2 * j;
            *(float2*)&fs[EMBF + m0 * ESTR + e0]       = make_float2(p.x, q.x);
            *(float2*)&fs[EMBF + (m0 + 1) * ESTR + e0] = make_float2(q.y, p.y);
        }
    __syncthreads();

    // ---- LN + GELU -> gT[e][tok], 2 tokens interleaved ----
    for (int tt = 0; tt < 16; tt += 2) {
        float v[2][4], s[2], qv[2], mu[2], inv[2];
#pragma unroll
        for (int u = 0; u < 2; u++) {
            const int t = wid * 16 + tt + u;
#pragma unroll
            for (int j = 0; j < 4; j++) {
                int e = lane + 32 * j;
                v[u][j] = fs[EMBF + t * ESTR + e] + fs[RNNF + e];
            }
            s[u] = v[u][0] + v[u][1] + v[u][2] + v[u][3];
        }
#pragma unroll
        for (int o = 16; o > 0; o >>= 1) {
            s[0] += __shfl_xor_sync(0xffffffffu, s[0], o);
            s[1] += __shfl_xor_sync(0xffffffffu, s[1], o);
        }
#pragma unroll
        for (int u = 0; u < 2; u++) {
            mu[u] = s[u] * (1.0f / 128.0f);
            float q = 0.f;
#pragma unroll
            for (int j = 0; j < 4; j++) { float d = v[u][j] - mu[u]; q += d * d; }
            qv[u] = q;
        }
#pragma unroll
        for (int o = 16; o > 0; o >>= 1) {
            qv[0] += __shfl_xor_sync(0xffffffffu, qv[0], o);
            qv[1] += __shfl_xor_sync(0xffffffffu, qv[1], o);
        }
#pragma unroll
        for (int u = 0; u < 2; u++) {
            inv[u] = rsqrtf(qv[u] * (1.0f / 128.0f) + 1e-5f);
            const int t = wid * 16 + tt + u;
#pragma unroll
            for (int j = 0; j < 4; j++) {
                int e = lane + 32 * j;
                float h = (v[u][j] - mu[u]) * inv[u] * fs[GAMF + e] + fs[BETF + e];
                fs[GTF + e * GTS + t] = 0.5f * h * (1.0f + erff(h * 0.70710678118654752f));
            }
        }
    }
    __syncthreads();

    // ---- GEMM2 (tiled scalar FFMA2): logits = g @ WdT ----
    {
        ull P2[4][4], Q2[4][4];
#pragma unroll
        for (int i = 0; i < 4; i++)
#pragma unroll
            for (int j = 0; j < 4; j++) { P2[i][j] = 0ull; Q2[i][j] = 0ull; }

#pragma unroll 4
        for (int e = 0; e < 128; ++e) {
            ulonglong2 aA = *(const ulonglong2*)&fs[GTF + e * GTS + 8 * tm];
            ulonglong2 aB = *(const ulonglong2*)&fs[GTF + e * GTS + 8 * tm + 4];
            ull av[4] = {aA.x, aA.y, aB.x, aB.y};
            ull sv[4] = {swp(aA.x), swp(aA.y), swp(aB.x), swp(aB.y)};
            ulonglong2 Bx = *(const ulonglong2*)&fs[WDTF + e * 128 + 4 * s0];
            ulonglong2 By = *(const ulonglong2*)&fs[WDTF + e * 128 + 4 * s1];
            ull bv[4] = {Bx.x, Bx.y, By.x, By.y};
#pragma unroll
            for (int i = 0; i < 4; i++)
#pragma unroll
                for (int j = 0; j < 4; j++) {
                    fma2(P2[i][j], av[i], bv[j]);
                    fma2(Q2[i][j], sv[i], bv[j]);
                }
        }
        __syncthreads();
#pragma unroll
        for (int i = 0; i < 4; i++)
#pragma unroll
            for (int j = 0; j < 4; j++) {
                float2 p = up2(P2[i][j]), q = up2(Q2[i][j]);
                int r0 = 8 * tm + 2 * i, c0 = 8 * te + 2 * j;
                *(float2*)&fs[EMBF + r0 * ESTR + c0]       = make_float2(p.x, q.y);
                *(float2*)&fs[EMBF + (r0 + 1) * ESTR + c0] = make_float2(q.x, p.y);
            }
    }
    __syncthreads();

    // ---- gumbel-sigmoid + round + exact top-k (2-bit search, 2 tokens paired) ----
    const int K = *topk_p;
    const float Kf = (float)K;
    const uint32_t ltm = (1u << lane) - 1u;

    for (int tt = 0; tt < 16; tt += 2) {
        float ap[2][4], bn[2][4], csum[2];
        uint32_t ub[2][4];
#pragma unroll
        for (int u = 0; u < 2; u++) {
            const int t = wid * 16 + tt + u;
            const int gt = t0 + t;
            float4 lgv = *(const float4*)&fs[EMBF + t * ESTR + lane * 4];
            float lg[4] = {lgv.x, lgv.y, lgv.z, lgv.w};
            float4 gu = *(const float4*)&gumbel[(size_t)gt * 128 + lane * 4];
            float gua[4] = {gu.x, gu.y, gu.z, gu.w};
            csum[u] = 0.f;
#pragma unroll
            for (int jj = 0; jj < 4; jj++) {
                float z = (lg[jj] + gua[jj] + 3.0f) * 2.5f;
                ap[u][jj] = 1.0f / (1.0f + expf(-z));
                bn[u][jj] = rintf(ap[u][jj]);
                csum[u] += bn[u][jj];
                ub[u][jj] = __float_as_uint(ap[u][jj]);
            }
        }
#pragma unroll
        for (int o = 16; o > 0; o >>= 1) {
            csum[0] += __shfl_xor_sync(0xffffffffu, csum[0], o);
            csum[1] += __shfl_xor_sync(0xffffffffu, csum[1], o);
        }

        int kneed[2], doSel[2];
        uint32_t T[2] = {0u, 0u};
#pragma unroll
        for (int u = 0; u < 2; u++) {
            doSel[u] = (csum[u] > Kf) || (csum[u] == 0.0f);
            kneed[u] = (csum[u] > Kf) ? K : 1;
        }

        // 15 steps x 2 bits: counts for 3 candidates packed (10-bit fields)
#pragma unroll
        for (int sh = 28; sh >= 0; sh -= 2) {
            int sred[2];
#pragma unroll
            for (int u = 0; u < 2; u++) {
                uint32_t c1 = T[u] | (1u << sh);
                uint32_t c2 = T[u] | (2u << sh);
                uint32_t c3 = T[u] | (3u << sh);
                int pc = 0;
#pragma unroll
                for (int jj = 0; jj < 4; jj++) {
                    pc += (ub[u][jj] >= c1) ? 1 : 0;
                    pc += (ub[u][jj] >= c2) ? (1 << 10) : 0;
                    pc += (ub[u][jj] >= c3) ? (1 << 20) : 0;
                }
                sred[u] = pc;
            }
            sred[0] = __reduce_add_sync(0xffffffffu, sred[0]);
            sred[1] = __reduce_add_sync(0xffffffffu, sred[1]);
#pragma unroll
            for (int u = 0; u < 2; u++) {
                int n1 = sred[u] & 1023, n2 = (sred[u] >> 10) & 1023, n3 = sred[u] >> 20;
                uint32_t v = (n3 >= kneed[u]) ? 3u : (n2 >= kneed[u]) ? 2u : (n1 >= kneed[u]) ? 1u : 0u;
                T[u] |= v << sh;
            }
        }

        int need[2];
#pragma unroll
        for (int u = 0; u < 2; u++) {
            need[u] = (ub[u][0] > T[u]) + (ub[u][1] > T[u]) + (ub[u][2] > T[u]) + (ub[u][3] > T[u]);
        }
        need[0] = kneed[0] - __reduce_add_sync(0xffffffffu, need[0]);
        need[1] = kneed[1] - __reduce_add_sync(0xffffffffu, need[1]);

#pragma unroll
        for (int u = 0; u < 2; u++) {
            const int t = wid * 16 + tt + u;
            const int gt = t0 + t;
            uint32_t bm[4];
#pragma unroll
            for (int jj = 0; jj < 4; jj++) bm[jj] = __ballot_sync(0xffffffffu, ub[u][jj] == T[u]);
            int base = __popc(bm[0] & ltm) + __popc(bm[1] & ltm) +
                       __popc(bm[2] & ltm) + __popc(bm[3] & ltm);
            int pre = 0;
            float ob[4];
#pragma unroll
            for (int jj = 0; jj < 4; jj++) {
                int tr = base + pre;
                float sel = (ub[u][jj] > T[u] || (ub[u][jj] == T[u] && tr < need[u])) ? 1.0f : 0.0f;
                ob[jj] = doSel[u] ? sel : bn[u][jj];
                pre += (bm[jj] >> lane) & 1u;
            }
            *(float4*)&out_bin[(size_t)gt * 128 + lane * 4] = make_float4(ob[0], ob[1], ob[2], ob[3]);
            if (out_ap)
                *(float4*)&out_ap[(size_t)gt * 128 + lane * 4] =
                    make_float4(ap[u][0], ap[u][1], ap[u][2], ap[u][3]);
        }
    }
}

extern "C" void kernel_launch(void* const* d_in, const int* in_sizes, int n_in,
                              void* d_out, int out_size) {
    const float* x        = (const float*)d_in[0];
    const float* W_router = (const float*)d_in[1];
    const float* W_dec    = (const float*)d_in[2];
    const float* ln_gamma = (const float*)d_in[3];
    const float* ln_beta  = (const float*)d_in[4];
    const float* rnn      = (const float*)d_in[5];
    const float* gumbel   = (const float*)d_in[6];
    const int*   topk     = (const int*)d_in[7];

    float* out_bin = (float*)d_out;
    const size_t N = (size_t)16384 * 128;
    float* out_ap = ((size_t)out_size >= 2 * N) ? out_bin + N : nullptr;

    prep_kernel<<<(128 * Dm) / 256, 256>>>(W_router, W_dec);

    cudaFuncSetAttribute(fused_kernel, cudaFuncAttributeMaxDynamicSharedMemorySize, SMEM_SZ);
    fused_kernel<<<16384 / MT, 256, SMEM_SZ>>>(
        x, gumbel, rnn, ln_gamma, ln_beta, topk, out_bin, out_ap);
}